// round 7
// baseline (speedup 1.0000x reference)
#include <cuda_runtime.h>
#include <math.h>

// ---------------------------------------------------------------------------
// AvULoss: N=2^21 rows, C=32. Persistent threads, 4 threads/row, NO smem,
// register double-buffered LDG.128 pipeline, quad shfl reduction per row,
// single block reduction at the end.
//   log2 domain: y = x*log2e, e = 2^y; S = sum e, dot = sum e*y
//   conf = 2^(m*log2e)/S ; unc = ln2*(log2 S - dot/S)
//   accurate = (x[label] == m)  (xlab extracted via SEL during the scan)
//   num = sum w*[accurate==certain], den = sum w
//   loss = -log(num/(den+1e-10) + 1e-10)
// Last-block ticket finalizes + resets accumulators (graph-replay safe).
// Labels arrive as int32 (JAX x64-disabled downcasts the int64 randint).
// ---------------------------------------------------------------------------

#define BLOCK 256
#define LOG2E 1.4426950408889634f
#define LN2   0.6931471805599453f

__device__ double g_acc[2];
__device__ unsigned int g_ticket = 0;

__device__ __forceinline__ float tanh_approx(float x) {
    float r;
    asm("tanh.approx.f32 %0, %1;" : "=f"(r) : "f"(x));
    return r;
}

__global__ __launch_bounds__(BLOCK, 5)
void avu_kernel(const float4* __restrict__ logits4,
                const int* __restrict__ labels,
                const float* __restrict__ unc_th_p,
                float* __restrict__ out,
                int N)
{
    __shared__ float sred[16];               // 8 warps x {num, den}
    __shared__ bool s_last;

    const int tid  = threadIdx.x;
    const int lane = tid & 31;
    const int quad = lane & 3;               // position within 4-thread row team
    const int base = quad * 8;               // this thread's first column

    int row = (blockIdx.x * BLOCK + tid) >> 2;          // first row for quad
    const int rstride = (gridDim.x * BLOCK) >> 2;       // rows per chip-iter
    const float th = __ldg(unc_th_p);

    float num = 0.f, den = 0.f;

    // ---- prefetch iteration 0 (clamped so loads are always legal) ----
    float4 a, b; int lab;
    {
        int r = row < N ? row : N - 1;
        const float4* p = logits4 + (size_t)r * 8 + quad * 2;
        a = p[0]; b = p[1];
        lab = labels[r];
    }

    while (row < N) {                        // uniform per warp (N % 8 == 0)
        int rnext = row + rstride;
        float4 an, bn; int labn;
        {
            int r = rnext < N ? rnext : N - 1;
            const float4* p = logits4 + (size_t)r * 8 + quad * 2;
            an = p[0]; bn = p[1];
            labn = labels[r];
        }

        // ---- compute current: S, dot, max, value-at-label over 8 elems ----
        float xs[8] = {a.x, a.y, a.z, a.w, b.x, b.y, b.z, b.w};
        float S = 0.f, dot = 0.f;
        float m = -3.402823466e+38f, xlab = -3.402823466e+38f;
#pragma unroll
        for (int j = 0; j < 8; ++j) {
            float x = xs[j];
            float y = x * LOG2E;
            float e = exp2f(y);
            S += e;
            dot = __fmaf_rn(e, y, dot);
            m = fmaxf(m, x);
            if (base + j == lab) xlab = x;
        }

        // ---- quad reduction (xor 1, 2) ----
#pragma unroll
        for (int o = 1; o < 4; o <<= 1) {
            S    += __shfl_xor_sync(0xffffffffu, S,    o);
            dot  += __shfl_xor_sync(0xffffffffu, dot,  o);
            m     = fmaxf(m,    __shfl_xor_sync(0xffffffffu, m,    o));
            xlab  = fmaxf(xlab, __shfl_xor_sync(0xffffffffu, xlab, o));
        }

        if (quad == 0) {
            float invS = __frcp_rn(S);
            float conf = exp2f(m * LOG2E) * invS;           // max softmax prob
            float unc  = LN2 * (__log2f(S) - dot * invS);   // predictive entropy
            bool accurate = (xlab == m);
            bool certain  = (unc <= th);
            float t = tanh_approx(unc);
            float w = (accurate ? conf : (1.f - conf)) * (certain ? (1.f - t) : t);
            if (accurate == certain) num += w;              // cats ac + iu
            den += w;
        }

        a = an; b = bn; lab = labn;
        row = rnext;
    }

    // ---- block reduction of (num, den), once ----
#pragma unroll
    for (int o = 16; o > 0; o >>= 1) {
        num += __shfl_down_sync(0xffffffffu, num, o);
        den += __shfl_down_sync(0xffffffffu, den, o);
    }
    const int wid = tid >> 5;
    if (lane == 0) {
        sred[wid]     = num;
        sred[wid + 8] = den;
    }
    __syncthreads();

    if (tid < 2) {
        double s = 0.0;
#pragma unroll
        for (int wv = 0; wv < 8; ++wv) s += (double)sred[tid * 8 + wv];
        atomicAdd(&g_acc[tid], s);
        __threadfence();
    }
    __syncthreads();

    // ---- last-block finalize + reset (graph-replay deterministic) ----
    if (tid == 0) {
        unsigned int ticket = atomicAdd(&g_ticket, 1u);
        s_last = (ticket == gridDim.x - 1u);
    }
    __syncthreads();
    if (s_last && tid == 0) {
        volatile double* acc = g_acc;
        double nsum = acc[0], dsum = acc[1];
        double avu = nsum / (dsum + 1e-10);
        out[0] = (float)(-log(avu + 1e-10));
        g_acc[0] = 0.0; g_acc[1] = 0.0;
        __threadfence();
        g_ticket = 0u;
    }
}

extern "C" void kernel_launch(void* const* d_in, const int* in_sizes, int n_in,
                              void* d_out, int out_size)
{
    const float4* logits4 = (const float4*)d_in[0];
    const int*    labels  = (const int*)d_in[1];
    const float*  unc_th  = (const float*)d_in[2];
    float* out = (float*)d_out;

    const int N = in_sizes[1];               // rows (2^21)
    int grid = 148 * 5;                      // matches __launch_bounds__(256,5)
    int maxBlocks = (N + (BLOCK / 4) - 1) / (BLOCK / 4);
    if (grid > maxBlocks) grid = maxBlocks;

    avu_kernel<<<grid, BLOCK>>>(logits4, labels, unc_th, out, N);
}